// round 1
// baseline (speedup 1.0000x reference)
#include <cuda_runtime.h>
#include <cstdint>

#define N 8400
#define WORDS 132          // ceil(8400/64)
#define SCORE_THR 0.5f
#define IOU_THR 0.5f
#define JSPLIT 4
#define JCHUNK 2100        // 8400 / 4, exact
#define ABLOCKS 33         // 33*256 = 8448 >= 8400

// ---- scratch (static device globals: allocation-free rule) ----
__device__ float4 g_ubox[N];                       // unsorted xyxy
__device__ float g_uscore[N];                      // unsorted score
__device__ unsigned long long g_key[N];            // sort keys
__device__ int g_rankp[JSPLIT][N];                 // partial ranks (no atomics, no init needed)
__device__ float4 g_sbox[N];                       // sorted xyxy
__device__ float g_sscore[N];                      // sorted score
__device__ unsigned long long g_mask[N][WORDS];    // IoU suppression bitmask (8.9 MB)
__device__ unsigned long long g_remv[WORDS];       // final removed bits
__device__ int g_nvalid;

// ---------------------------------------------------------------
// K1: decode boxes + build 64-bit sort keys.
// key = descending score, tie-break ascending index; invalid scores sort last
// (still index-ascending among themselves — their output rows are zeroed, so
// only "all-valid-first" matters, but we keep it exact anyway).
// ---------------------------------------------------------------
__global__ void k_decode(const float* __restrict__ in) {
    int a = blockIdx.x * blockDim.x + threadIdx.x;
    if (a >= N) return;
    float cx = in[a];
    float cy = in[N + a];
    float w  = in[2 * N + a];
    float h  = in[3 * N + a];
    float s  = in[4 * N + a];
    float hw = __fmul_rn(w, 0.5f);   // == w/2 exactly
    float hh = __fmul_rn(h, 0.5f);
    float4 b;
    b.x = __fsub_rn(cx, hw);
    b.y = __fsub_rn(cy, hh);
    b.z = __fadd_rn(cx, hw);
    b.w = __fadd_rn(cy, hh);
    g_ubox[a] = b;
    g_uscore[a] = s;
    unsigned long long tie = (unsigned long long)(16383 - a);
    unsigned long long key = (s >= SCORE_THR)
        ? ((((unsigned long long)__float_as_uint(s)) << 14) | tie)
        : tie;   // all invalid keys < any valid key
    g_key[a] = key;
}

// ---------------------------------------------------------------
// K2: rank by counting (keys are unique -> rank is a permutation).
// Each block counts one 2100-key chunk against 256 anchors.
// ---------------------------------------------------------------
__global__ void k_rank() {
    __shared__ unsigned long long sk[JCHUNK];
    int jbase = blockIdx.y * JCHUNK;
    for (int d = threadIdx.x; d < JCHUNK; d += blockDim.x)
        sk[d] = g_key[jbase + d];
    __syncthreads();
    int a = blockIdx.x * blockDim.x + threadIdx.x;
    if (a >= N) return;
    unsigned long long ka = g_key[a];
    int cnt = 0;
#pragma unroll 4
    for (int d = 0; d < JCHUNK; ++d)
        cnt += (sk[d] > ka) ? 1 : 0;
    g_rankp[blockIdx.y][a] = cnt;
}

// ---------------------------------------------------------------
// K3: scatter into sorted order.
// ---------------------------------------------------------------
__global__ void k_scatter() {
    int a = blockIdx.x * blockDim.x + threadIdx.x;
    if (a >= N) return;
    int rank = g_rankp[0][a] + g_rankp[1][a] + g_rankp[2][a] + g_rankp[3][a];
    g_sbox[rank]   = g_ubox[a];
    g_sscore[rank] = g_uscore[a];
}

// ---------------------------------------------------------------
// K4: IoU suppression bitmask, upper triangle only, valid rows/cols only.
// All fp math via _rn intrinsics to match per-op IEEE fp32 (no FMA fusion),
// replicating reference op order exactly.
// ---------------------------------------------------------------
__global__ void k_mask() {
    int rb = blockIdx.y, cb = blockIdx.x;
    if (cb < rb) return;   // uniform early exit, before any sync
    __shared__ float4 cbox[64];
    __shared__ float carea[64];
    __shared__ float cscore[64];
    int t = threadIdx.x;   // 64 threads
    int j = cb * 64 + t;
    if (j < N) {
        float4 b = g_sbox[j];
        cbox[t] = b;
        carea[t] = __fmul_rn(__fsub_rn(b.z, b.x), __fsub_rn(b.w, b.y));
        cscore[t] = g_sscore[j];
    } else {
        cscore[t] = -1.0f;
    }
    __syncthreads();
    int i = rb * 64 + t;
    if (i >= N) return;
    float si = g_sscore[i];
    if (si < SCORE_THR) return;   // row is invalid (i >= V); never read by reduce
    float4 bi = g_sbox[i];
    float ai = __fmul_rn(__fsub_rn(bi.z, bi.x), __fsub_rn(bi.w, bi.y));
    unsigned long long bits = 0ull;
#pragma unroll 8
    for (int d = 0; d < 64; ++d) {
        int jj = cb * 64 + d;
        if (jj <= i) continue;             // upper triangle only
        if (cscore[d] < SCORE_THR) continue; // invalid cols never need suppression
        float4 bj = cbox[d];
        float ltx = fmaxf(bi.x, bj.x);
        float lty = fmaxf(bi.y, bj.y);
        float rbx = fminf(bi.z, bj.z);
        float rby = fminf(bi.w, bj.w);
        float wx = fmaxf(__fsub_rn(rbx, ltx), 0.0f);
        float wy = fmaxf(__fsub_rn(rby, lty), 0.0f);
        float inter = __fmul_rn(wx, wy);
        float uni = __fsub_rn(__fadd_rn(ai, carea[d]), inter);
        float iou = __fdiv_rn(inter, fmaxf(uni, 1e-9f));
        if (iou > IOU_THR) bits |= (1ull << d);
    }
    g_mask[i][cb] = bits;
}

// ---------------------------------------------------------------
// K5: greedy NMS reduce (single block, tiled).
// Per 64-row tile: thread 0 does the sequential intra-tile bit scan using the
// diagonal mask words; then all threads apply the kept rows' mask words to the
// remaining words in parallel (shared atomicOr).
// ---------------------------------------------------------------
__global__ void k_reduce() {
    __shared__ unsigned long long remv[WORDS];
    __shared__ unsigned long long diag[64];
    __shared__ int s_rows[64];
    __shared__ int s_nk;
    __shared__ int s_V;
    int tid = threadIdx.x;
    if (tid == 0) s_V = 0;
    if (tid < WORDS) remv[tid] = 0ull;
    __syncthreads();

    // count valid (V): all valid entries occupy sorted positions [0, V)
    int cnt = 0;
    for (int p = tid; p < N; p += blockDim.x)
        cnt += (g_sscore[p] >= SCORE_THR) ? 1 : 0;
    for (int o = 16; o > 0; o >>= 1)
        cnt += __shfl_down_sync(0xffffffffu, cnt, o);
    if ((tid & 31) == 0 && cnt) atomicAdd(&s_V, cnt);
    __syncthreads();
    int V = s_V;
    int T = (V + 63) >> 6;

    for (int t = 0; t < T; ++t) {
        if (tid < 64) {
            int i = t * 64 + tid;
            diag[tid] = (i < V) ? g_mask[i][t] : 0ull;
        }
        __syncthreads();
        if (tid == 0) {
            unsigned long long cur = remv[t];
            int rem = V - t * 64;
            if (rem < 64) cur |= (~0ull) << rem;   // rows >= V: treat as removed
            int nk = 0;
            for (int b = 0; b < 64; ++b) {
                if (!((cur >> b) & 1ull)) {
                    s_rows[nk++] = t * 64 + b;     // this row is KEPT
                    cur |= diag[b];                // it suppresses later bits in this word
                }
            }
            remv[t] = cur;
            s_nk = nk;
        }
        __syncthreads();
        int nwords = T - 1 - t;                    // only words < T matter
        int total = nwords * s_nk;
        for (int p = tid; p < total; p += blockDim.x) {
            int w = t + 1 + (p % nwords);
            int r = s_rows[p / nwords];
            unsigned long long m = g_mask[r][w];
            if (m) atomicOr(&remv[w], m);
        }
        __syncthreads();
    }

    if (tid < WORDS) g_remv[tid] = remv[tid];
    if (tid == 0) g_nvalid = V;
}

// ---------------------------------------------------------------
// K6: emit output rows: kept -> [x1,y1,x2,y2,score], else zeros.
// ---------------------------------------------------------------
__global__ void k_output(float* __restrict__ out) {
    int p = blockIdx.x * blockDim.x + threadIdx.x;
    if (p >= N) return;
    int V = g_nvalid;
    bool kept = (p < V) && !((g_remv[p >> 6] >> (p & 63)) & 1ull);
    float4 b = g_sbox[p];
    float s = g_sscore[p];
    out[p * 5 + 0] = kept ? b.x : 0.0f;
    out[p * 5 + 1] = kept ? b.y : 0.0f;
    out[p * 5 + 2] = kept ? b.z : 0.0f;
    out[p * 5 + 3] = kept ? b.w : 0.0f;
    out[p * 5 + 4] = kept ? s   : 0.0f;
}

extern "C" void kernel_launch(void* const* d_in, const int* in_sizes, int n_in,
                              void* d_out, int out_size) {
    const float* in = (const float*)d_in[0];
    float* out = (float*)d_out;
    k_decode<<<ABLOCKS, 256>>>(in);
    k_rank<<<dim3(ABLOCKS, JSPLIT), 256>>>();
    k_scatter<<<ABLOCKS, 256>>>();
    k_mask<<<dim3(WORDS, WORDS), 64>>>();
    k_reduce<<<1, 1024>>>();
    k_output<<<ABLOCKS, 256>>>(out);
}